// round 1
// baseline (speedup 1.0000x reference)
#include <cuda_runtime.h>
#include <cuda_bf16.h>
#include <math.h>

// ---------------------------------------------------------------------------
// SentenceEncoder: 12-layer BERT-base, B=8 S=1024 D=768 H=12 HD=64 FF=3072
// Round 1: exact-fp32 SIMT implementation (correctness first, ~50-65ms est).
// ---------------------------------------------------------------------------

#define NB    8
#define SEQ   1024
#define NTOK  (NB * SEQ)        // 8192
#define DM    768
#define DFF   3072
#define NH    12
#define HD    64
#define NL    12

// ------------------------- scratch (device globals) ------------------------
__device__ float g_h   [NTOK * DM];
__device__ float g_q   [NTOK * DM];
__device__ float g_k   [NTOK * DM];
__device__ float g_v   [NTOK * DM];
__device__ float g_ctx [NTOK * DM];
__device__ float g_t1  [NTOK * DM];
__device__ float g_ao  [NTOK * DM];
__device__ float g_int [NTOK * DFF];
__device__ int   g_len [NB];

// ------------------------------ helpers ------------------------------------
__device__ __forceinline__ float gelu_exact(float x) {
    return 0.5f * x * (1.0f + erff(x * 0.70710678118654752f));
}

// block-wide (256 threads) reduction of (sum, sumsq)
__device__ __forceinline__ void block_reduce2(float& sum, float& sq) {
    #pragma unroll
    for (int o = 16; o > 0; o >>= 1) {
        sum += __shfl_xor_sync(0xffffffffu, sum, o);
        sq  += __shfl_xor_sync(0xffffffffu, sq, o);
    }
    __shared__ float rs[8], rq[8];
    int w = threadIdx.x >> 5;
    if ((threadIdx.x & 31) == 0) { rs[w] = sum; rq[w] = sq; }
    __syncthreads();
    sum = 0.0f; sq = 0.0f;
    #pragma unroll
    for (int i = 0; i < 8; i++) { sum += rs[i]; sq += rq[i]; }
}

__device__ __forceinline__ float block_reduce1(float v) {
    #pragma unroll
    for (int o = 16; o > 0; o >>= 1)
        v += __shfl_xor_sync(0xffffffffu, v, o);
    __shared__ float r[8];
    int w = threadIdx.x >> 5;
    if ((threadIdx.x & 31) == 0) r[w] = v;
    __syncthreads();
    float t = 0.0f;
    #pragma unroll
    for (int i = 0; i < 8; i++) t += r[i];
    return t;
}

// ---------------------------- embeddings + LN -------------------------------
// one block per token, 256 threads, 3 elems/thread (768 = 3*256)
__global__ void embed_ln_kernel(const int* __restrict__ ids,
                                const float* __restrict__ we,
                                const float* __restrict__ pe,
                                const float* __restrict__ te,
                                const float* __restrict__ gam,
                                const float* __restrict__ bet,
                                float* __restrict__ out) {
    int tok = blockIdx.x;
    int s   = tok & (SEQ - 1);
    int id  = ids[tok];
    const float* wrow = we + (size_t)id * DM;
    const float* prow = pe + (size_t)s * DM;
    float x[3];
    float sum = 0.0f, sq = 0.0f;
    #pragma unroll
    for (int i = 0; i < 3; i++) {
        int d = threadIdx.x + (i << 8);
        float t = wrow[d] + prow[d] + te[d];
        x[i] = t; sum += t; sq += t * t;
    }
    block_reduce2(sum, sq);
    float mean = sum * (1.0f / DM);
    float var  = sq * (1.0f / DM) - mean * mean;
    float inv  = rsqrtf(var + 1e-12f);
    float* op = out + (size_t)tok * DM;
    #pragma unroll
    for (int i = 0; i < 3; i++) {
        int d = threadIdx.x + (i << 8);
        op[d] = (x[i] - mean) * inv * gam[d] + bet[d];
    }
}

// ---------------------- residual add + LayerNorm ----------------------------
__global__ void add_ln_kernel(const float* __restrict__ x,
                              const float* __restrict__ res,
                              const float* __restrict__ gam,
                              const float* __restrict__ bet,
                              float* __restrict__ out) {
    int tok = blockIdx.x;
    const float* xp = x   + (size_t)tok * DM;
    const float* rp = res + (size_t)tok * DM;
    float v[3];
    float sum = 0.0f, sq = 0.0f;
    #pragma unroll
    for (int i = 0; i < 3; i++) {
        int d = threadIdx.x + (i << 8);
        float t = xp[d] + rp[d];
        v[i] = t; sum += t; sq += t * t;
    }
    block_reduce2(sum, sq);
    float mean = sum * (1.0f / DM);
    float var  = sq * (1.0f / DM) - mean * mean;
    float inv  = rsqrtf(var + 1e-12f);
    float* op = out + (size_t)tok * DM;
    #pragma unroll
    for (int i = 0; i < 3; i++) {
        int d = threadIdx.x + (i << 8);
        op[d] = (v[i] - mean) * inv * gam[d] + bet[d];
    }
}

// ------------------------------ lengths -------------------------------------
__global__ void length_kernel(const int* __restrict__ mask, int* __restrict__ len) {
    int b = blockIdx.x;
    int v = 0;
    for (int i = threadIdx.x; i < SEQ; i += 256) v += mask[b * SEQ + i];
    #pragma unroll
    for (int o = 16; o > 0; o >>= 1)
        v += __shfl_xor_sync(0xffffffffu, v, o);
    __shared__ int ri[8];
    int w = threadIdx.x >> 5;
    if ((threadIdx.x & 31) == 0) ri[w] = v;
    __syncthreads();
    if (threadIdx.x == 0) {
        int t = 0;
        #pragma unroll
        for (int i = 0; i < 8; i++) t += ri[i];
        len[b] = t;
    }
}

// ------------------------------- GEMM ---------------------------------------
// C[M,N] = act( A[M,K] @ B[K,N] + bias[N] )
// block tile 128x128, K-tile 16, 256 threads, 8x8 per thread (fp32 exact).
// M = 8192 fixed by grid.y = 64; N, K multiples of 128 / 16.
__global__ void __launch_bounds__(256)
gemm_bias_kernel(const float* __restrict__ A, const float* __restrict__ B,
                 const float* __restrict__ bias, float* __restrict__ C,
                 int K, int N, int act) {
    __shared__ float As[16][128];
    __shared__ float Bs[16][128];
    const int tid = threadIdx.x;
    const int tx  = tid & 15, ty = tid >> 4;
    const int m0  = blockIdx.y << 7, n0 = blockIdx.x << 7;
    const int ar  = tid >> 2;          // 0..63
    const int ac  = (tid & 3) << 2;    // 0,4,8,12
    const int br  = tid >> 5;          // 0..7
    const int bc  = (tid & 31) << 2;   // 0..124

    float acc[8][8];
    #pragma unroll
    for (int i = 0; i < 8; i++)
        #pragma unroll
        for (int j = 0; j < 8; j++) acc[i][j] = 0.0f;

    const float* Ap0 = A + (size_t)(m0 + ar) * K + ac;
    const float* Ap1 = A + (size_t)(m0 + 64 + ar) * K + ac;
    const float* Bp0 = B + (size_t)br * N + n0 + bc;
    const float* Bp1 = B + (size_t)(br + 8) * N + n0 + bc;

    for (int k0 = 0; k0 < K; k0 += 16) {
        float4 a0 = *(const float4*)(Ap0 + k0);
        float4 a1 = *(const float4*)(Ap1 + k0);
        float4 b0 = *(const float4*)(Bp0 + (size_t)k0 * N);
        float4 b1 = *(const float4*)(Bp1 + (size_t)k0 * N);
        __syncthreads();   // protect smem of previous iteration
        As[ac + 0][ar] = a0.x; As[ac + 1][ar] = a0.y;
        As[ac + 2][ar] = a0.z; As[ac + 3][ar] = a0.w;
        As[ac + 0][64 + ar] = a1.x; As[ac + 1][64 + ar] = a1.y;
        As[ac + 2][64 + ar] = a1.z; As[ac + 3][64 + ar] = a1.w;
        *(float4*)&Bs[br][bc]     = b0;
        *(float4*)&Bs[br + 8][bc] = b1;
        __syncthreads();
        #pragma unroll
        for (int kk = 0; kk < 16; kk++) {
            float a[8], b[8];
            *(float4*)&a[0] = *(const float4*)&As[kk][ty << 2];
            *(float4*)&a[4] = *(const float4*)&As[kk][64 + (ty << 2)];
            *(float4*)&b[0] = *(const float4*)&Bs[kk][tx << 2];
            *(float4*)&b[4] = *(const float4*)&Bs[kk][64 + (tx << 2)];
            #pragma unroll
            for (int i = 0; i < 8; i++)
                #pragma unroll
                for (int j = 0; j < 8; j++)
                    acc[i][j] = fmaf(a[i], b[j], acc[i][j]);
        }
    }

    #pragma unroll
    for (int i = 0; i < 8; i++) {
        int r = m0 + ((i < 4) ? ((ty << 2) + i) : (64 + (ty << 2) + i - 4));
        #pragma unroll
        for (int jg = 0; jg < 2; jg++) {
            int c = n0 + jg * 64 + (tx << 2);
            float4 o;
            o.x = acc[i][jg * 4 + 0] + bias[c + 0];
            o.y = acc[i][jg * 4 + 1] + bias[c + 1];
            o.z = acc[i][jg * 4 + 2] + bias[c + 2];
            o.w = acc[i][jg * 4 + 3] + bias[c + 3];
            if (act) {
                o.x = gelu_exact(o.x); o.y = gelu_exact(o.y);
                o.z = gelu_exact(o.z); o.w = gelu_exact(o.w);
            }
            *(float4*)(C + (size_t)r * N + c) = o;
        }
    }
}

// ------------------------------ attention -----------------------------------
// flash-style, fp32. grid (S/64, H, B), 256 threads. q/k/v/ctx are [tok, 768]
// with head h occupying columns [h*64, h*64+64).
// Key tiles beyond len[b] are skipped (post-softmax mask == masked softmax).
#define ATT_PITCH 65
#define ATT_SMEM  (4 * 64 * ATT_PITCH * 4)   // Qs, Ks, Vs, Ps = 66560 B

__global__ void __launch_bounds__(256)
attention_kernel(const float* __restrict__ q, const float* __restrict__ kx,
                 const float* __restrict__ vx, const int* __restrict__ lens,
                 float* __restrict__ ctx) {
    extern __shared__ float smem[];
    float* Qs = smem;
    float* Ks = smem + 64 * ATT_PITCH;
    float* Vs = smem + 2 * 64 * ATT_PITCH;
    float* Ps = smem + 3 * 64 * ATT_PITCH;

    const int tid = threadIdx.x;
    const int tx  = tid & 15, ty = tid >> 4;
    const int qt  = blockIdx.x, hh = blockIdx.y, b = blockIdx.z;
    const int L   = lens[b];
    const size_t base = ((size_t)b * SEQ) * DM + (size_t)hh * HD;

    for (int idx = tid; idx < 64 * 64; idx += 256) {
        int r = idx >> 6, d = idx & 63;
        Qs[r * ATT_PITCH + d] = q[base + (size_t)(qt * 64 + r) * DM + d];
    }

    float acc[16];
    float mi[4], li[4];
    #pragma unroll
    for (int i = 0; i < 16; i++) acc[i] = 0.0f;
    #pragma unroll
    for (int i = 0; i < 4; i++) { mi[i] = -1e30f; li[i] = 0.0f; }

    const int ntiles = (L + 63) >> 6;
    for (int t = 0; t < ntiles; t++) {
        __syncthreads();   // previous iteration consumers of Ks/Vs/Ps done
        for (int idx = tid; idx < 64 * 64; idx += 256) {
            int r = idx >> 6, d = idx & 63;
            size_t g = base + (size_t)(t * 64 + r) * DM + d;
            Ks[r * ATT_PITCH + d] = kx[g];
            Vs[r * ATT_PITCH + d] = vx[g];
        }
        __syncthreads();

        float s[16];
        #pragma unroll
        for (int i = 0; i < 16; i++) s[i] = 0.0f;
        for (int d = 0; d < 64; d++) {
            float qa[4], kb[4];
            #pragma unroll
            for (int i = 0; i < 4; i++) qa[i] = Qs[((ty << 2) + i) * ATT_PITCH + d];
            #pragma unroll
            for (int j = 0; j < 4; j++) kb[j] = Ks[((tx << 2) + j) * ATT_PITCH + d];
            #pragma unroll
            for (int i = 0; i < 4; i++)
                #pragma unroll
                for (int j = 0; j < 4; j++)
                    s[i * 4 + j] = fmaf(qa[i], kb[j], s[i * 4 + j]);
        }
        // scale + key mask
        #pragma unroll
        for (int j = 0; j < 4; j++) {
            bool valid = (t * 64 + (tx << 2) + j) < L;
            #pragma unroll
            for (int i = 0; i < 4; i++)
                s[i * 4 + j] = valid ? s[i * 4 + j] * 0.125f : -1e30f;
        }
        // online softmax per row (reduce across 16 tx lanes within half-warp)
        #pragma unroll
        for (int i = 0; i < 4; i++) {
            float rm = fmaxf(fmaxf(s[i*4+0], s[i*4+1]), fmaxf(s[i*4+2], s[i*4+3]));
            #pragma unroll
            for (int o = 1; o < 16; o <<= 1)
                rm = fmaxf(rm, __shfl_xor_sync(0xffffffffu, rm, o));
            float nm = fmaxf(mi[i], rm);
            float ps = 0.0f;
            #pragma unroll
            for (int j = 0; j < 4; j++) {
                float p = __expf(s[i * 4 + j] - nm);
                s[i * 4 + j] = p;
                ps += p;
            }
            #pragma unroll
            for (int o = 1; o < 16; o <<= 1)
                ps += __shfl_xor_sync(0xffffffffu, ps, o);
            float corr = __expf(mi[i] - nm);
            li[i] = li[i] * corr + ps;
            mi[i] = nm;
            #pragma unroll
            for (int j = 0; j < 4; j++) acc[i * 4 + j] *= corr;
            #pragma unroll
            for (int j = 0; j < 4; j++)
                Ps[((ty << 2) + i) * ATT_PITCH + (tx << 2) + j] = s[i * 4 + j];
        }
        __syncthreads();
        // O += P @ V
        for (int kk = 0; kk < 64; kk++) {
            float pa[4], vb[4];
            #pragma unroll
            for (int i = 0; i < 4; i++) pa[i] = Ps[((ty << 2) + i) * ATT_PITCH + kk];
            #pragma unroll
            for (int j = 0; j < 4; j++) vb[j] = Vs[kk * ATT_PITCH + (tx << 2) + j];
            #pragma unroll
            for (int i = 0; i < 4; i++)
                #pragma unroll
                for (int j = 0; j < 4; j++)
                    acc[i * 4 + j] = fmaf(pa[i], vb[j], acc[i * 4 + j]);
        }
    }

    #pragma unroll
    for (int i = 0; i < 4; i++) {
        float inv = 1.0f / li[i];
        #pragma unroll
        for (int j = 0; j < 4; j++)
            ctx[base + (size_t)(qt * 64 + (ty << 2) + i) * DM + (tx << 2) + j]
                = acc[i * 4 + j] * inv;
    }
}

// ----------------------- masked mean pool + L2 norm -------------------------
__global__ void pool_kernel(const float* __restrict__ h, const int* __restrict__ len,
                            float* __restrict__ out) {
    int b = blockIdx.x;
    int L = len[b];
    const float* hb = h + (size_t)b * SEQ * DM;
    float s0 = 0.0f, s1 = 0.0f, s2 = 0.0f;
    for (int t = 0; t < L; t++) {
        const float* row = hb + (size_t)t * DM;
        s0 += row[threadIdx.x];
        s1 += row[threadIdx.x + 256];
        s2 += row[threadIdx.x + 512];
    }
    float invL = 1.0f / (float)L;
    float m0 = s0 * invL, m1 = s1 * invL, m2 = s2 * invL;
    float nsq = block_reduce1(m0 * m0 + m1 * m1 + m2 * m2);
    float norm = fmaxf(sqrtf(nsq), 1e-12f);
    float inv = 1.0f / norm;
    out[b * DM + threadIdx.x]       = m0 * inv;
    out[b * DM + threadIdx.x + 256] = m1 * inv;
    out[b * DM + threadIdx.x + 512] = m2 * inv;
}

// ------------------------------- launcher -----------------------------------
extern "C" void kernel_launch(void* const* d_in, const int* in_sizes, int n_in,
                              void* d_out, int out_size) {
    (void)in_sizes; (void)n_in; (void)out_size;
    const int*   input_ids = (const int*)  d_in[0];
    const int*   amask     = (const int*)  d_in[1];
    const float* word_emb  = (const float*)d_in[2];
    const float* pos_emb   = (const float*)d_in[3];
    const float* type_emb  = (const float*)d_in[4];
    const float* emb_ln_s  = (const float*)d_in[5];
    const float* emb_ln_b  = (const float*)d_in[6];
    const float* Wq  = (const float*)d_in[7];
    const float* bq  = (const float*)d_in[8];
    const float* Wk  = (const float*)d_in[9];
    const float* bk  = (const float*)d_in[10];
    const float* Wv  = (const float*)d_in[11];
    const float* bv  = (const float*)d_in[12];
    const float* Wao = (const float*)d_in[13];
    const float* bao = (const float*)d_in[14];
    const float* l1s = (const float*)d_in[15];
    const float* l1b = (const float*)d_in[16];
    const float* Wi  = (const float*)d_in[17];
    const float* bi  = (const float*)d_in[18];
    const float* Wmo = (const float*)d_in[19];
    const float* bmo = (const float*)d_in[20];
    const float* l2s = (const float*)d_in[21];
    const float* l2b = (const float*)d_in[22];

    float *h, *qb, *kb, *vb, *cx, *t1, *ao, *inter;
    int* len;
    cudaGetSymbolAddress((void**)&h,     g_h);
    cudaGetSymbolAddress((void**)&qb,    g_q);
    cudaGetSymbolAddress((void**)&kb,    g_k);
    cudaGetSymbolAddress((void**)&vb,    g_v);
    cudaGetSymbolAddress((void**)&cx,    g_ctx);
    cudaGetSymbolAddress((void**)&t1,    g_t1);
    cudaGetSymbolAddress((void**)&ao,    g_ao);
    cudaGetSymbolAddress((void**)&inter, g_int);
    cudaGetSymbolAddress((void**)&len,   g_len);

    cudaFuncSetAttribute(attention_kernel,
                         cudaFuncAttributeMaxDynamicSharedMemorySize, ATT_SMEM);

    embed_ln_kernel<<<NTOK, 256>>>(input_ids, word_emb, pos_emb, type_emb,
                                   emb_ln_s, emb_ln_b, h);
    length_kernel<<<NB, 256>>>(amask, len);

    dim3 gD(DM / 128, NTOK / 128);    // 6 x 64
    dim3 gF(DFF / 128, NTOK / 128);   // 24 x 64
    dim3 gA(SEQ / 64, NH, NB);        // 16 x 12 x 8

    for (int l = 0; l < NL; l++) {
        const float* wq = Wq + (size_t)l * DM * DM;
        const float* wk = Wk + (size_t)l * DM * DM;
        const float* wv = Wv + (size_t)l * DM * DM;
        const float* wo = Wao + (size_t)l * DM * DM;
        const float* wi = Wi + (size_t)l * DM * DFF;
        const float* wm = Wmo + (size_t)l * DFF * DM;

        gemm_bias_kernel<<<gD, 256>>>(h, wq, bq + l * DM, qb, DM, DM, 0);
        gemm_bias_kernel<<<gD, 256>>>(h, wk, bk + l * DM, kb, DM, DM, 0);
        gemm_bias_kernel<<<gD, 256>>>(h, wv, bv + l * DM, vb, DM, DM, 0);

        attention_kernel<<<gA, 256, ATT_SMEM>>>(qb, kb, vb, len, cx);

        gemm_bias_kernel<<<gD, 256>>>(cx, wo, bao + l * DM, t1, DM, DM, 0);
        add_ln_kernel<<<NTOK, 256>>>(t1, h, l1s + l * DM, l1b + l * DM, ao);

        gemm_bias_kernel<<<gF, 256>>>(ao, wi, bi + l * DFF, inter, DM, DFF, 1);
        gemm_bias_kernel<<<gD, 256>>>(inter, wm, bmo + l * DM, t1, DFF, DM, 0);
        add_ln_kernel<<<NTOK, 256>>>(t1, ao, l2s + l * DM, l2b + l * DM, h);
    }

    pool_kernel<<<NB, 256>>>(h, len, (float*)d_out);
}